// round 6
// baseline (speedup 1.0000x reference)
#include <cuda_runtime.h>
#include <cuda_bf16.h>
#include <stdint.h>
#include <math.h>

#define NRO 32768   /* 64*512 rows */
#define NF  1024    /* 64*16 flat rows */
#define NC  8192    /* codes */
#define KEMB 768
#define NS  16

// ---------------- device scratch (no allocation allowed) -------------------
__device__ __align__(16) float g_x[NRO*32];
__device__ __align__(16) float g_qkv[NRO*96];
__device__ __align__(16) float g_o[NRO*32];
__device__ __align__(16) float g_xs[NF*32];
__device__ __align__(16) float g_xc[NF*KEMB];
__device__ float g_A[NF];
__device__ float g_B[NC];
__device__ __align__(16) float g_logits[(size_t)NF*NC];
__device__ int   g_cand[(size_t)NF*NC];
__device__ int   g_cnt[NF];
__device__ int   g_win[NS*NF];
__device__ int   g_variant;

// ---------------- helpers --------------------------------------------------
__device__ __forceinline__ float expf_acc(float x){
  if (x < -87.3f) return 0.0f;
  float k = rintf(x * 1.44269504088896341f);
  float r = fmaf(k, -0.693359375f, x);
  r = fmaf(k, 2.12194440e-4f, r);
  float p = 1.9841270e-4f;
  p = fmaf(p, r, 1.3888889e-3f);
  p = fmaf(p, r, 8.3333338e-3f);
  p = fmaf(p, r, 4.1666668e-2f);
  p = fmaf(p, r, 1.6666667e-1f);
  p = fmaf(p, r, 0.5f);
  p = fmaf(p, r, 1.0f);
  p = fmaf(p, r, 1.0f);
  return p * __int_as_float(((int)k + 127) << 23);
}

__device__ __forceinline__ uint32_t rotl32(uint32_t x, int r){ return (x<<r)|(x>>(32-r)); }

// generic threefry2x32 cipher, 20 rounds, arbitrary key
__device__ __forceinline__ void tf2(uint32_t k0, uint32_t k1, uint32_t x0, uint32_t x1,
                                    uint32_t& o0, uint32_t& o1){
  uint32_t k2 = 0x1BD11BDAu ^ k0 ^ k1;
  x0 += k0; x1 += k1;
#define R4(a,b,c,d) {x0+=x1;x1=rotl32(x1,a);x1^=x0; x0+=x1;x1=rotl32(x1,b);x1^=x0; x0+=x1;x1=rotl32(x1,c);x1^=x0; x0+=x1;x1=rotl32(x1,d);x1^=x0;}
  R4(13,15,26,6)  x0 += k1; x1 += k2 + 1u;
  R4(17,29,16,24) x0 += k2; x1 += k0 + 2u;
  R4(13,15,26,6)  x0 += k0; x1 += k1 + 3u;
  R4(17,29,16,24) x0 += k1; x1 += k2 + 4u;
  R4(13,15,26,6)  x0 += k2; x1 += k0 + 5u;
#undef R4
  o0 = x0; o1 = x1;
}

// variant-parametric random bits for key (0,42), flat index i in array of 2^27
// v=0: legacy halves-split; v=1: partitionable low word (out1);
// v=2: partitionable high word (out0); v=3: partitionable xor fold.
__device__ __forceinline__ uint32_t jax_bits_v(uint32_t i, int v){
  uint32_t o0, o1;
  if (v == 0){
    if (i < 67108864u){ tf2(0u,42u, i, i+67108864u, o0,o1); return o0; }
    tf2(0u,42u, i-67108864u, i, o0,o1); return o1;
  }
  tf2(0u,42u, 0u, i, o0,o1);
  return (v==1) ? o1 : (v==2) ? o0 : (o0 ^ o1);
}

// ---------------- RNG stream oracle ----------------------------------------
// Reproduce attn_mask = randint(split(key(0),16)[1], (64,496), 0, 2) under each
// stream convention and compare with the actual input. For span=2 randint
// reduces to lower_bits & 1 with lower_bits = random_bits(k2'),
// (k1',k2') = split(ks1). Select the matching variant; 999 if none.
__global__ __launch_bounds__(256) void k_oracle(const int* __restrict__ mask){
  __shared__ int ok[4];
  int tid = threadIdx.x;
  if (tid < 4) ok[tid] = 1;
  __syncthreads();
  for (int v = 0; v < 4; v++){
    uint32_t k2a, k2b;
    if (v == 0){
      // legacy split(key0,16): counts 0..31 halves; ks1=(o0(E(2,18)), o0(E(3,19)))
      uint32_t s0,s1,d0,d1;
      tf2(0u,0u, 2u,18u, s0,d0);
      tf2(0u,0u, 3u,19u, s1,d1);
      // legacy split(ks1,2): counts 0..3; k2' = (o1(E(0,2)), o1(E(1,3)))
      uint32_t a0,a1,b0,b1;
      tf2(s0,s1, 0u,2u, a0,a1);
      tf2(s0,s1, 1u,3u, b0,b1);
      k2a = a1; k2b = b1;
    } else {
      // foldlike split: child j = full pair of E(0, j)
      uint32_t p0,p1,q0,q1;
      tf2(0u,0u, 0u,1u, p0,p1);      // ks1 = E_{key0}(0,1)
      tf2(p0,p1, 0u,1u, q0,q1);      // k2' = E_{ks1}(0,1)
      k2a = q0; k2b = q1;
    }
    bool good = true;
    for (int i = tid; i < 31744; i += 256){
      uint32_t o0,o1,bits;
      if (v == 0){
        if (i < 15872){ tf2(k2a,k2b,(uint32_t)i,(uint32_t)(i+15872),o0,o1); bits = o0; }
        else          { tf2(k2a,k2b,(uint32_t)(i-15872),(uint32_t)i,o0,o1); bits = o1; }
      } else {
        tf2(k2a,k2b, 0u, (uint32_t)i, o0,o1);
        bits = (v==1) ? o1 : (v==2) ? o0 : (o0 ^ o1);
      }
      if ((int)(bits & 1u) != mask[i]){ good = false; break; }
    }
    if (!good) atomicAnd(&ok[v], 0);
  }
  __syncthreads();
  if (tid == 0){
    int sel = 999;
    if (ok[0]) sel = 0;
    else if (ok[1]) sel = 1;
    else if (ok[2]) sel = 2;
    else if (ok[3]) sel = 3;
    g_variant = sel;
  }
}

// ---------------- passthrough copy -----------------------------------------
__global__ void k_copy(const float4* __restrict__ s, float4* __restrict__ d, int n4){
  int i = blockIdx.x*blockDim.x + threadIdx.x;
  if (i < n4) d[i] = s[i];
}

// ---------------- generic C = A*B^T tiled GEMM -----------------------------
template<int BM,int BN,int BK,int TM,int TN,int EPI>
__global__ __launch_bounds__((BM/TM)*(BN/TN)) void k_gemm(
    const float* __restrict__ A, const float* __restrict__ B,
    const float* __restrict__ bias, float* __restrict__ C, int K, int Nld,
    const float* __restrict__ rowt, const float* __restrict__ colt)
{
  constexpr int NT = (BM/TM)*(BN/TN);
  __shared__ float As[BK][BM];
  __shared__ float Bs[BK][BN];
  const int m0 = blockIdx.x*BM, n0 = blockIdx.y*BN;
  const int tid = threadIdx.x;
  const int tx = tid % (BN/TN), ty = tid / (BN/TN);
  float acc[TM][TN];
#pragma unroll
  for (int i=0;i<TM;i++)
#pragma unroll
    for (int j=0;j<TN;j++) acc[i][j]=0.f;

  for (int k0=0;k0<K;k0+=BK){
#pragma unroll
    for (int idx=tid; idx<BM*BK/4; idx+=NT){
      int mm = idx/(BK/4), kk = (idx%(BK/4))*4;
      float4 v = *(const float4*)(A + (size_t)(m0+mm)*K + k0+kk);
      As[kk+0][mm]=v.x; As[kk+1][mm]=v.y; As[kk+2][mm]=v.z; As[kk+3][mm]=v.w;
    }
#pragma unroll
    for (int idx=tid; idx<BN*BK/4; idx+=NT){
      int nn = idx/(BK/4), kk = (idx%(BK/4))*4;
      float4 v = *(const float4*)(B + (size_t)(n0+nn)*K + k0+kk);
      Bs[kk+0][nn]=v.x; Bs[kk+1][nn]=v.y; Bs[kk+2][nn]=v.z; Bs[kk+3][nn]=v.w;
    }
    __syncthreads();
#pragma unroll
    for (int kt=0;kt<BK;kt++){
      float a[TM], b[TN];
#pragma unroll
      for (int i=0;i<TM/4;i++){
        float4 v = *(const float4*)&As[kt][ty*TM+i*4];
        a[i*4]=v.x; a[i*4+1]=v.y; a[i*4+2]=v.z; a[i*4+3]=v.w;
      }
#pragma unroll
      for (int j=0;j<TN/4;j++){
        float4 v = *(const float4*)&Bs[kt][tx*TN+j*4];
        b[j*4]=v.x; b[j*4+1]=v.y; b[j*4+2]=v.z; b[j*4+3]=v.w;
      }
#pragma unroll
      for (int i=0;i<TM;i++)
#pragma unroll
        for (int j=0;j<TN;j++) acc[i][j] = fmaf(a[i], b[j], acc[i][j]);
    }
    __syncthreads();
  }
#pragma unroll
  for (int i=0;i<TM;i++){
    int m = m0 + ty*TM + i;
#pragma unroll
    for (int j=0;j<TN;j++){
      int n = n0 + tx*TN + j;
      float v = acc[i][j];
      if (EPI==0){ v = __fadd_rn(v, bias[n]); }
      else {
        float t1 = __fadd_rn(rowt[m], colt[n]);
        float t2 = __fsub_rn(t1, __fmul_rn(2.0f, v));
        v = __fadd_rn(-t2, -1e-5f);
      }
      C[(size_t)m*Nld + n] = v;
    }
  }
}

// ---------------- qkv: thread per row, W[96][32] in smem --------------------
__global__ __launch_bounds__(256) void k_qkv(const float* __restrict__ W,
                                             const float* __restrict__ bias){
  __shared__ float Ws[96*32], bs[96];
  int tid = threadIdx.x;
  for (int i=tid;i<96*32;i+=256) Ws[i]=W[i];
  if (tid<96) bs[tid]=bias[tid];
  __syncthreads();
  int row = blockIdx.x*256 + tid;
  float x[32];
#pragma unroll
  for (int i=0;i<8;i++){
    float4 v = *(const float4*)&g_x[(size_t)row*32 + i*4];
    x[i*4]=v.x; x[i*4+1]=v.y; x[i*4+2]=v.z; x[i*4+3]=v.w;
  }
  for (int n=0;n<96;n++){
    float s = bs[n];
#pragma unroll
    for (int k=0;k<32;k++) s = fmaf(x[k], Ws[n*32+k], s);
    g_qkv[(size_t)row*96 + n] = s;
  }
}

// ---------------- attention: block per (b,h) --------------------------------
__global__ __launch_bounds__(256) void k_attn(const int* __restrict__ mask){
  int b = blockIdx.x >> 2, h = blockIdx.x & 3;
  __shared__ float ks[512][8], vs[512][8];
  __shared__ unsigned char mk[512];
  int tid = threadIdx.x;
  for (int i=tid;i<512*8;i+=256){
    int t = i>>3, d = i&7;
    size_t base = (size_t)(b*512+t)*96;
    ks[t][d] = g_qkv[base + 32 + h*8 + d];
    vs[t][d] = g_qkv[base + 64 + h*8 + d];
  }
  for (int t=tid;t<512;t+=256)
    mk[t] = (t<16) ? 1 : (unsigned char)(mask[b*496 + t-16] != 0);
  __syncthreads();
  for (int tq=tid; tq<512; tq+=256){
    size_t qb = (size_t)(b*512+tq)*96 + h*8;
    float q[8];
#pragma unroll
    for (int d=0;d<8;d++) q[d] = g_qkv[qb+d];
    float mv = -INFINITY, ls = 0.f, acc[8];
#pragma unroll
    for (int d=0;d<8;d++) acc[d]=0.f;
    for (int t=0;t<512;t++){
      float dot = 0.f;
#pragma unroll
      for (int d=0;d<8;d++) dot = fmaf(q[d], ks[t][d], dot);
      float sc = mk[t] ? __fdiv_rn(dot, 2.82842712474619f) : -1e9f;
      float nm = fmaxf(mv, sc);
      float rs = expf_acc(mv - nm);
      float p  = expf_acc(sc - nm);
      ls = ls*rs + p;
#pragma unroll
      for (int d=0;d<8;d++) acc[d] = fmaf(acc[d], rs, p*vs[t][d]);
      mv = nm;
    }
    size_t ob = (size_t)(b*512+tq)*32 + h*8;
#pragma unroll
    for (int d=0;d<8;d++) g_o[ob+d] = __fdiv_rn(acc[d], ls);
  }
}

// ---------------- out-proj + residual + LN1 --------------------------------
__global__ __launch_bounds__(256) void k_proj_ln(const float* __restrict__ W,
    const float* __restrict__ bias, const float* __restrict__ gam,
    const float* __restrict__ bet){
  __shared__ float Ws[32*32], bs[32], gs[32], es[32];
  int tid = threadIdx.x;
  for (int i=tid;i<1024;i+=256) Ws[i]=W[i];
  if (tid<32){ bs[tid]=bias[tid]; gs[tid]=gam[tid]; es[tid]=bet[tid]; }
  __syncthreads();
  int row = blockIdx.x*256 + tid;
  float o[32], t[32];
#pragma unroll
  for (int i=0;i<32;i++) o[i] = g_o[(size_t)row*32+i];
  float mu = 0.f;
#pragma unroll
  for (int i=0;i<32;i++){
    float y = bs[i];
#pragma unroll
    for (int k=0;k<32;k++) y = fmaf(o[k], Ws[i*32+k], y);
    t[i] = g_x[(size_t)row*32+i] + y;
    mu += t[i];
  }
  mu = __fdiv_rn(mu, 32.f);
  float var = 0.f;
#pragma unroll
  for (int i=0;i<32;i++){ float d = t[i]-mu; var = fmaf(d,d,var); }
  var = __fdiv_rn(var, 32.f);
  float sd = __fsqrt_rn(var + 1e-5f);
#pragma unroll
  for (int i=0;i<32;i++)
    g_x[(size_t)row*32+i] = fmaf(gs[i], __fdiv_rn(t[i]-mu, sd), es[i]);
}

// ---------------- FF + residual + LN2 (+compact cq rows on last layer) ------
__global__ __launch_bounds__(256) void k_ff_ln(const float* __restrict__ W1,
    const float* __restrict__ b1, const float* __restrict__ W2,
    const float* __restrict__ b2, const float* __restrict__ gam,
    const float* __restrict__ bet, int save_cq){
  __shared__ float W1s[64*32], W2s[32*64], b1s[64], b2s[32], gs[32], es[32];
  int tid = threadIdx.x;
  for (int i=tid;i<2048;i+=256){ W1s[i]=W1[i]; W2s[i]=W2[i]; }
  if (tid<64) b1s[tid]=b1[tid];
  if (tid<32){ b2s[tid]=b2[tid]; gs[tid]=gam[tid]; es[tid]=bet[tid]; }
  __syncthreads();
  int row = blockIdx.x*256 + tid;
  float x[32], h[64], t[32];
#pragma unroll
  for (int i=0;i<32;i++) x[i] = g_x[(size_t)row*32+i];
#pragma unroll
  for (int j=0;j<64;j++){
    float s = b1s[j];
#pragma unroll
    for (int k=0;k<32;k++) s = fmaf(x[k], W1s[j*32+k], s);
    h[j] = fmaxf(s, 0.f);
  }
  float mu = 0.f;
#pragma unroll
  for (int i=0;i<32;i++){
    float y = b2s[i];
#pragma unroll
    for (int j=0;j<64;j++) y = fmaf(h[j], W2s[i*64+j], y);
    t[i] = x[i] + y;
    mu += t[i];
  }
  mu = __fdiv_rn(mu, 32.f);
  float var = 0.f;
#pragma unroll
  for (int i=0;i<32;i++){ float d = t[i]-mu; var = fmaf(d,d,var); }
  var = __fdiv_rn(var, 32.f);
  float sd = __fsqrt_rn(var + 1e-5f);
  int tq = row & 511, bb = row >> 9;
#pragma unroll
  for (int i=0;i<32;i++){
    float v = fmaf(gs[i], __fdiv_rn(t[i]-mu, sd), es[i]);
    g_x[(size_t)row*32+i] = v;
    if (save_cq && tq < 16) g_xs[(size_t)(bb*16+tq)*32 + i] = v;
  }
}

// ---------------- row sum-of-squares (f64 accumulate), warp per row ---------
__global__ __launch_bounds__(256) void k_ssq(const float* __restrict__ X,
                                             float* __restrict__ out, int nrows){
  int w = (blockIdx.x*256 + threadIdx.x) >> 5;
  int lane = threadIdx.x & 31;
  if (w >= nrows) return;
  const float* r = X + (size_t)w*KEMB;
  double s = 0.0;
  for (int j=lane; j<KEMB; j+=32){ double v = (double)r[j]; s += v*v; }
#pragma unroll
  for (int o=16;o;o>>=1) s += __shfl_xor_sync(0xffffffffu, s, o);
  if (lane==0) out[w] = (float)s;
}

// ---------------- candidates: block per flat row ----------------------------
__global__ __launch_bounds__(256) void k_cand(){
  int n = blockIdx.x, tid = threadIdx.x;
  const float* L = g_logits + (size_t)n*NC;
  __shared__ float smax[8];
  __shared__ int cnt;
  float m = -INFINITY;
  for (int k=tid;k<NC;k+=256) m = fmaxf(m, L[k]);
#pragma unroll
  for (int o=16;o;o>>=1) m = fmaxf(m, __shfl_xor_sync(0xffffffffu, m, o));
  if ((tid&31)==0) smax[tid>>5] = m;
  if (tid==0) cnt = 0;
  __syncthreads();
  m = smax[0];
#pragma unroll
  for (int i=1;i<8;i++) m = fmaxf(m, smax[i]);
  float thr = m - 20.45f;   // gumbel span 20.4121 + slack
  int* cd = g_cand + (size_t)n*NC;
  for (int k=tid;k<NC;k+=256)
    if (L[k] >= thr){ int p = atomicAdd(&cnt, 1); cd[p] = k; }
  __syncthreads();
  if (tid==0) g_cnt[n] = cnt;
}

// ---------------- gumbel-max sampling: block per flat row -------------------
__global__ __launch_bounds__(256) void k_sample(){
  int n = blockIdx.x, tid = threadIdx.x;
  const float* L = g_logits + (size_t)n*NC;
  const int* cd = g_cand + (size_t)n*NC;
  int cn = g_cnt[n];
  int v = g_variant;
  __shared__ float bz[8]; __shared__ int bk[8];
  if (v > 3){
    // oracle found no matching stream: emit distinctive diagnostic (code 0)
    if (tid < NS)
      for (int s=tid; s<NS; s+=256) g_win[s*NF + n] = 0;
    return;
  }
  for (int s=0;s<NS;s++){
    float best = -INFINITY; int bidx = NC;
    for (int i=tid;i<cn;i+=256){
      int k = cd[i];
      uint32_t idx = ((uint32_t)s<<23) + ((uint32_t)n<<13) + (uint32_t)k;
      uint32_t bits = jax_bits_v(idx, v);
      float f = __uint_as_float((bits>>9) | 0x3f800000u) - 1.0f;
      float u = (f == 0.0f) ? 1.17549435e-38f : f;
      float nl = -(float)log((double)u);
      float gmb = -(float)log((double)nl);
      float z = __fadd_rn(L[k], gmb);
      if (z > best || (z == best && k < bidx)){ best = z; bidx = k; }
    }
#pragma unroll
    for (int o=16;o;o>>=1){
      float oz = __shfl_xor_sync(0xffffffffu, best, o);
      int   ok = __shfl_xor_sync(0xffffffffu, bidx, o);
      if (oz > best || (oz == best && ok < bidx)){ best = oz; bidx = ok; }
    }
    if ((tid&31)==0){ bz[tid>>5] = best; bk[tid>>5] = bidx; }
    __syncthreads();
    if (tid==0){
      float bb = bz[0]; int bi = bk[0];
#pragma unroll
      for (int i=1;i<8;i++)
        if (bz[i] > bb || (bz[i] == bb && bk[i] < bi)){ bb = bz[i]; bi = bk[i]; }
      g_win[s*NF + n] = bi;
    }
    __syncthreads();
  }
}

// ---------------- final: out = xq, block per flat row -----------------------
__global__ __launch_bounds__(256) void k_out(const float* __restrict__ cb,
                                             float* __restrict__ out){
  int n = blockIdx.x, tid = threadIdx.x;
  __shared__ int wi[NS];
  if (tid < NS) wi[tid] = g_win[tid*NF + n];
  __syncthreads();
  for (int c=tid;c<KEMB;c+=256){
    float s = 0.f;
#pragma unroll
    for (int i=0;i<NS;i++) s = __fadd_rn(s, cb[(size_t)wi[i]*KEMB + c]);
    float xq = __fmul_rn(s, 0.0625f);
    float xc = g_xc[(size_t)n*KEMB + c];
    out[(size_t)n*KEMB + c] = __fadd_rn(xc, __fsub_rn(xq, xc));
  }
}

// ---------------- launch ----------------------------------------------------
extern "C" void kernel_launch(void* const* d_in, const int* in_sizes, int n_in,
                              void* d_out, int out_size){
  const float* xcq      = (const float*)d_in[0];
  const int*   amask    = (const int*)  d_in[1];
  const float* fc_in_w  = (const float*)d_in[2];
  const float* fc_in_b  = (const float*)d_in[3];
  const float* fc_out_w = (const float*)d_in[4];
  const float* fc_out_b = (const float*)d_in[5];
  const float* enc_in_w = (const float*)d_in[6];
  const float* enc_in_b = (const float*)d_in[7];
  const float* enc_out_w= (const float*)d_in[8];
  const float* enc_out_b= (const float*)d_in[9];
  const float* ff1_w    = (const float*)d_in[10];
  const float* ff1_b    = (const float*)d_in[11];
  const float* ff2_w    = (const float*)d_in[12];
  const float* ff2_b    = (const float*)d_in[13];
  const float* ln1_g    = (const float*)d_in[14];
  const float* ln1_b    = (const float*)d_in[15];
  const float* ln2_g    = (const float*)d_in[16];
  const float* ln2_b    = (const float*)d_in[17];
  const float* codebook = (const float*)d_in[18];
  float* out = (float*)d_out;

  float *gx, *gxs, *gxc, *gA, *gB, *glog;
  cudaGetSymbolAddress((void**)&gx,  g_x);
  cudaGetSymbolAddress((void**)&gxs, g_xs);
  cudaGetSymbolAddress((void**)&gxc, g_xc);
  cudaGetSymbolAddress((void**)&gA,  g_A);
  cudaGetSymbolAddress((void**)&gB,  g_B);
  cudaGetSymbolAddress((void**)&glog,g_logits);

  // RNG stream self-calibration against the attn_mask input
  k_oracle<<<1, 256>>>(amask);

  // passthrough: out[786432:] = xcq
  k_copy<<<24576, 256>>>((const float4*)xcq, (float4*)(out + NF*KEMB), 6291456);

  // x = xcq @ fc_in_w^T + b   [32768, 32]
  k_gemm<128,32,32,4,4,0><<<dim3(NRO/128,1), 256>>>(
      xcq, fc_in_w, fc_in_b, gx, KEMB, 32, nullptr, nullptr);

  for (int l=0;l<2;l++){
    k_qkv<<<NRO/256, 256>>>(enc_in_w + (size_t)l*96*32, enc_in_b + (size_t)l*96);
    k_attn<<<256, 256>>>(amask);
    k_proj_ln<<<NRO/256, 256>>>(enc_out_w + (size_t)l*1024, enc_out_b + (size_t)l*32,
                                ln1_g + (size_t)l*32, ln1_b + (size_t)l*32);
    k_ff_ln<<<NRO/256, 256>>>(ff1_w + (size_t)l*2048, ff1_b + (size_t)l*64,
                              ff2_w + (size_t)l*2048, ff2_b + (size_t)l*32,
                              ln2_g + (size_t)l*32, ln2_b + (size_t)l*32,
                              (l==1) ? 1 : 0);
  }

  // xc_out = xs @ fc_out_w^T + b   [1024, 768]
  k_gemm<64,64,32,4,4,0><<<dim3(NF/64, KEMB/64), 256>>>(
      gxs, fc_out_w, fc_out_b, gxc, 32, KEMB, nullptr, nullptr);

  // row/col squared norms
  k_ssq<<<NF/8, 256>>>(gxc, gA, NF);
  k_ssq<<<NC/8, 256>>>(codebook, gB, NC);

  // logits = -((A + B) - 2 * xc@cb^T) - 1e-5   [1024, 8192]
  k_gemm<128,128,16,8,8,1><<<dim3(NF/128, NC/128), 256>>>(
      gxc, codebook, nullptr, glog, KEMB, NC, gA, gB);

  k_cand<<<NF, 256>>>();
  k_sample<<<NF, 256>>>();
  k_out<<<NF, 256>>>(codebook, out);
}